// round 1
// baseline (speedup 1.0000x reference)
#include <cuda_runtime.h>

// Problem constants (fixed by the dataset)
#define BV 4
#define HV 8
#define TV 8192
#define DV 64
#define BHV 32            // B*H
#define CHUNKS 32         // T-chunks per head in pass 1
#define CHTOK 256         // tokens per chunk
#define TILE 64           // tokens per inner tile
#define NTILE 4           // CHTOK / TILE

#define LN_EPS 1e-5f
#define DEN_EPS 1e-6f

// Scratch (allocation-free: __device__ globals)
__device__ float g_kproj[(size_t)BHV * TV * DV];           // 64 MB: k_proj[bh][t][m]
__device__ float g_part[(size_t)BHV * CHUNKS * DV * DV];   // 16 MB: partial kv per (bh,chunk)
__device__ float g_kv[(size_t)BHV * DV * DV];              // 512 KB: kv[bh][m][n]

__device__ __forceinline__ float wredsum(float v) {
    v += __shfl_xor_sync(0xffffffffu, v, 16);
    v += __shfl_xor_sync(0xffffffffu, v, 8);
    v += __shfl_xor_sync(0xffffffffu, v, 4);
    v += __shfl_xor_sync(0xffffffffu, v, 2);
    v += __shfl_xor_sync(0xffffffffu, v, 1);
    return v;
}

__device__ __forceinline__ float featexp(float x) {
    return __expf(fminf(fmaxf(x, -15.f), 15.f)) * 0.1f;
}

#define MMA4x4(acc, a4, b4) do { \
    acc[0][0] += a4.x * b4.x; acc[0][1] += a4.x * b4.y; acc[0][2] += a4.x * b4.z; acc[0][3] += a4.x * b4.w; \
    acc[1][0] += a4.y * b4.x; acc[1][1] += a4.y * b4.y; acc[1][2] += a4.y * b4.z; acc[1][3] += a4.y * b4.w; \
    acc[2][0] += a4.z * b4.x; acc[2][1] += a4.z * b4.y; acc[2][2] += a4.z * b4.z; acc[2][3] += a4.z * b4.w; \
    acc[3][0] += a4.w * b4.x; acc[3][1] += a4.w * b4.y; acc[3][2] += a4.w * b4.z; acc[3][3] += a4.w * b4.w; \
} while (0)

// ---------------------------------------------------------------------------
// Pass 1: per (bh, chunk): LN+L2(k) -> kn, LN(v) -> vn, kp = exp(kn@proj)*0.1,
//         store kp to g_kproj, accumulate partial kv[m][n] += kp[t][m]*vn[t][n]
// ---------------------------------------------------------------------------
extern "C" __global__ void __launch_bounds__(256) fa_pass1(
    const float* __restrict__ k, const float* __restrict__ v,
    const float* __restrict__ proj, const float* __restrict__ gamma,
    const float* __restrict__ beta)
{
    extern __shared__ float sm[];
    float* s_proj = sm;                 // 4096  proj[n][m]
    float* s_knT  = sm + 4096;          // 4352  knT[n][t], stride 68
    float* s_vn   = s_knT + 4352;       // 4096  vn[t][n]
    float* s_kp   = s_vn + 4096;        // 4096  kp[t][m]

    const int tid = threadIdx.x, lane = tid & 31, warp = tid >> 5;
    const int bh = blockIdx.y, ch = blockIdx.x;

    for (int i = tid; i < 1024; i += 256)
        ((float4*)s_proj)[i] = ((const float4*)proj)[i];

    const float g0 = gamma[lane], g1 = gamma[lane + 32];
    const float be0 = beta[lane], be1 = beta[lane + 32];

    const float* kb = k + ((size_t)bh * TV + (size_t)ch * CHTOK) * DV;
    const float* vb = v + ((size_t)bh * TV + (size_t)ch * CHTOK) * DV;

    float accv[4][4];
#pragma unroll
    for (int i = 0; i < 4; i++)
#pragma unroll
        for (int j = 0; j < 4; j++) accv[i][j] = 0.f;

    const int r4 = (tid >> 4) * 4;   // row group (tokens in GEMM1, m in GEMM2)
    const int c4 = (tid & 15) * 4;   // col group (m in GEMM1, n in GEMM2)

    __syncthreads();

    for (int tile = 0; tile < NTILE; ++tile) {
        const int t0 = tile * TILE;

        // --- LN + L2 for k, LN for v (warp per token, 8 tokens/warp) ---
        for (int tt = 0; tt < 8; ++tt) {
            const int t = warp * 8 + tt;
            const float* kr = kb + (size_t)(t0 + t) * DV;
            float x0 = kr[lane], x1 = kr[lane + 32];
            float s  = wredsum(x0 + x1);
            float ss = wredsum(x0 * x0 + x1 * x1);
            float mu = s * (1.f / 64.f);
            float rstd = rsqrtf(ss * (1.f / 64.f) - mu * mu + LN_EPS);
            float y0 = (x0 - mu) * rstd * g0 + be0;
            float y1 = (x1 - mu) * rstd * g1 + be1;
            float n2 = wredsum(y0 * y0 + y1 * y1);
            float inv = 1.f / fmaxf(sqrtf(n2), 1e-12f);
            s_knT[lane * 68 + t] = y0 * inv;
            s_knT[(lane + 32) * 68 + t] = y1 * inv;

            const float* vr = vb + (size_t)(t0 + t) * DV;
            float w0 = vr[lane], w1 = vr[lane + 32];
            float sv  = wredsum(w0 + w1);
            float ssv = wredsum(w0 * w0 + w1 * w1);
            float muv = sv * (1.f / 64.f);
            float rsv = rsqrtf(ssv * (1.f / 64.f) - muv * muv + LN_EPS);
            s_vn[t * 64 + lane]      = (w0 - muv) * rsv * g0 + be0;
            s_vn[t * 64 + lane + 32] = (w1 - muv) * rsv * g1 + be1;
        }
        __syncthreads();

        // --- GEMM1: kp[t][m] = featexp(sum_n knT[n][t] * proj[n][m]) ---
        {
            float acc[4][4];
#pragma unroll
            for (int i = 0; i < 4; i++)
#pragma unroll
                for (int j = 0; j < 4; j++) acc[i][j] = 0.f;
#pragma unroll 8
            for (int n = 0; n < 64; ++n) {
                float4 a4 = *(const float4*)(s_knT + n * 68 + r4);
                float4 b4 = *(const float4*)(s_proj + n * 64 + c4);
                MMA4x4(acc, a4, b4);
            }
#pragma unroll
            for (int i = 0; i < 4; i++) {
                float4 r;
                r.x = featexp(acc[i][0]); r.y = featexp(acc[i][1]);
                r.z = featexp(acc[i][2]); r.w = featexp(acc[i][3]);
                *(float4*)(s_kp + (r4 + i) * 64 + c4) = r;
            }
        }
        __syncthreads();

        // --- store kp tile to global scratch (coalesced) ---
        {
            float* kpd = g_kproj + ((size_t)bh * TV + (size_t)ch * CHTOK + t0) * DV;
            for (int i = tid; i < 1024; i += 256)
                ((float4*)kpd)[i] = ((const float4*)s_kp)[i];
        }

        // --- GEMM2: accv[m][n] += kp[t][m] * vn[t][n] over tile ---
#pragma unroll 8
        for (int t = 0; t < 64; ++t) {
            float4 a4 = *(const float4*)(s_kp + t * 64 + r4);
            float4 b4 = *(const float4*)(s_vn + t * 64 + c4);
            MMA4x4(accv, a4, b4);
        }
        __syncthreads();
    }

    // --- write partial kv ---
    float* pd = g_part + (size_t)(bh * CHUNKS + ch) * 4096;
#pragma unroll
    for (int i = 0; i < 4; i++) {
        float4 r = { accv[i][0], accv[i][1], accv[i][2], accv[i][3] };
        *(float4*)(pd + (r4 + i) * 64 + c4) = r;
    }
}

// ---------------------------------------------------------------------------
// Reduce: kv[bh][e] = 0.1 * sum_c partial[bh][c][e]
// ---------------------------------------------------------------------------
extern "C" __global__ void __launch_bounds__(256) fa_reduce()
{
    const int idx = blockIdx.x * 256 + threadIdx.x;   // 0 .. 131071
    const int bh = idx >> 12, e = idx & 4095;
    const float* p = g_part + (size_t)bh * CHUNKS * 4096 + e;
    float s = 0.f;
#pragma unroll
    for (int c = 0; c < CHUNKS; ++c) s += p[(size_t)c * 4096];
    g_kv[idx] = s * 0.1f;
}

// ---------------------------------------------------------------------------
// Pass 2: qn -> qp, qkv = 0.1 * qp@kv, denom = max(sum qp*kp, eps), final LN
// ---------------------------------------------------------------------------
extern "C" __global__ void __launch_bounds__(256) fa_pass2(
    const float* __restrict__ q, const float* __restrict__ proj,
    const float* __restrict__ gamma, const float* __restrict__ beta,
    float* __restrict__ out)
{
    extern __shared__ float sm[];
    float* s_proj = sm;                  // 4096  proj[n][m]
    float* s_kv   = sm + 4096;           // 4096  kv[m][n]
    float* s_qnT  = sm + 8192;           // 4352  qnT[n][t] stride 68 (reused as qkv[t][n])
    float* s_qpT  = sm + 8192 + 4352;    // 4352  qpT[m][t] stride 68
    float* s_den  = sm + 8192 + 8704;    // 64

    const int tid = threadIdx.x, lane = tid & 31, warp = tid >> 5;
    const int bh = blockIdx.y, tile = blockIdx.x;   // tile of 64 tokens

    for (int i = tid; i < 1024; i += 256)
        ((float4*)s_proj)[i] = ((const float4*)proj)[i];
    {
        const float* kvg = g_kv + (size_t)bh * 4096;
        for (int i = tid; i < 1024; i += 256)
            ((float4*)s_kv)[i] = ((const float4*)kvg)[i];
    }

    const float g0 = gamma[lane], g1 = gamma[lane + 32];
    const float be0 = beta[lane], be1 = beta[lane + 32];

    const float* qb = q + ((size_t)bh * TV + (size_t)tile * 64) * DV;

    // --- LN + L2 of q (warp per token) ---
    for (int tt = 0; tt < 8; ++tt) {
        const int t = warp * 8 + tt;
        const float* qr = qb + (size_t)t * DV;
        float x0 = qr[lane], x1 = qr[lane + 32];
        float s  = wredsum(x0 + x1);
        float ss = wredsum(x0 * x0 + x1 * x1);
        float mu = s * (1.f / 64.f);
        float rstd = rsqrtf(ss * (1.f / 64.f) - mu * mu + LN_EPS);
        float y0 = (x0 - mu) * rstd * g0 + be0;
        float y1 = (x1 - mu) * rstd * g1 + be1;
        float n2 = wredsum(y0 * y0 + y1 * y1);
        float inv = 1.f / fmaxf(sqrtf(n2), 1e-12f);
        s_qnT[lane * 68 + t] = y0 * inv;
        s_qnT[(lane + 32) * 68 + t] = y1 * inv;
    }
    __syncthreads();

    // --- GEMM1: qpT[m][t] = featexp(sum_n proj[n][m] * qnT[n][t]) ---
    {
        const int mr = (tid >> 4) * 4, tc = (tid & 15) * 4;
        float acc[4][4];
#pragma unroll
        for (int i = 0; i < 4; i++)
#pragma unroll
            for (int j = 0; j < 4; j++) acc[i][j] = 0.f;
#pragma unroll 8
        for (int n = 0; n < 64; ++n) {
            float4 p4 = *(const float4*)(s_proj + n * 64 + mr);
            float4 q4 = *(const float4*)(s_qnT + n * 68 + tc);
            MMA4x4(acc, p4, q4);
        }
#pragma unroll
        for (int i = 0; i < 4; i++) {
            float4 r;
            r.x = featexp(acc[i][0]); r.y = featexp(acc[i][1]);
            r.z = featexp(acc[i][2]); r.w = featexp(acc[i][3]);
            *(float4*)(s_qpT + (mr + i) * 68 + tc) = r;
        }
    }
    __syncthreads();

    float* s_qkv = s_qnT;  // alias (qnT reads are done)

    // --- GEMM2: qkv[t][n] = 0.1 * sum_m qpT[m][t] * kv[m][n] ---
    {
        const int tr = (tid >> 4) * 4, nc = (tid & 15) * 4;
        float acc2[4][4];
#pragma unroll
        for (int i = 0; i < 4; i++)
#pragma unroll
            for (int j = 0; j < 4; j++) acc2[i][j] = 0.f;
#pragma unroll 8
        for (int m = 0; m < 64; ++m) {
            float4 a4 = *(const float4*)(s_qpT + m * 68 + tr);
            float4 b4 = *(const float4*)(s_kv + m * 64 + nc);
            MMA4x4(acc2, a4, b4);
        }
#pragma unroll
        for (int i = 0; i < 4; i++) {
            float4 r = { acc2[i][0] * 0.1f, acc2[i][1] * 0.1f,
                         acc2[i][2] * 0.1f, acc2[i][3] * 0.1f };
            *(float4*)(s_qkv + (tr + i) * 64 + nc) = r;
        }
    }

    // --- denom[t] = max(sum_m qp[t][m]*kp[t][m], eps) ---
    {
        const float* kpg = g_kproj + ((size_t)bh * TV + (size_t)tile * 64) * DV;
        for (int tt = 0; tt < 8; ++tt) {
            const int t = warp * 8 + tt;
            float d = s_qpT[lane * 68 + t] * kpg[(size_t)t * 64 + lane]
                    + s_qpT[(lane + 32) * 68 + t] * kpg[(size_t)t * 64 + lane + 32];
            d = wredsum(d);
            if (lane == 0) s_den[t] = fmaxf(d, DEN_EPS);
        }
    }
    __syncthreads();

    // --- final LN over qkv/denom, write out ---
    float* ob = out + ((size_t)bh * TV + (size_t)tile * 64) * DV;
    for (int tt = 0; tt < 8; ++tt) {
        const int t = warp * 8 + tt;
        const float inv_d = 1.f / s_den[t];
        float x0 = s_qkv[t * 64 + lane] * inv_d;
        float x1 = s_qkv[t * 64 + lane + 32] * inv_d;
        float s  = wredsum(x0 + x1);
        float ss = wredsum(x0 * x0 + x1 * x1);
        float mu = s * (1.f / 64.f);
        float rstd = rsqrtf(ss * (1.f / 64.f) - mu * mu + LN_EPS);
        ob[(size_t)t * 64 + lane]      = (x0 - mu) * rstd * g0 + be0;
        ob[(size_t)t * 64 + lane + 32] = (x1 - mu) * rstd * g1 + be1;
    }
}

// ---------------------------------------------------------------------------
extern "C" void kernel_launch(void* const* d_in, const int* in_sizes, int n_in,
                              void* d_out, int out_size)
{
    const float* q     = (const float*)d_in[0];
    const float* k     = (const float*)d_in[1];
    const float* v     = (const float*)d_in[2];
    const float* proj  = (const float*)d_in[3];
    const float* gamma = (const float*)d_in[4];
    const float* beta  = (const float*)d_in[5];
    float* out = (float*)d_out;

    // >48KB dynamic smem opt-in (idempotent, capture-safe: no stream ops)
    cudaFuncSetAttribute(fa_pass1, cudaFuncAttributeMaxDynamicSharedMemorySize, 66560);
    cudaFuncSetAttribute(fa_pass2, cudaFuncAttributeMaxDynamicSharedMemorySize, 67840);

    fa_pass1<<<dim3(CHUNKS, BHV), 256, 66560>>>(k, v, proj, gamma, beta);
    fa_reduce<<<512, 256>>>();
    fa_pass2<<<dim3(TV / 64, BHV), 256, 67840>>>(q, proj, gamma, beta, out);
}